// round 3
// baseline (speedup 1.0000x reference)
#include <cuda_runtime.h>
#include <cuda_bf16.h>

// ---------------------------------------------------------------------------
// G2EquivariantFeedForward, GB300 sm_103a — round 3
//
// Closed form: upd = a*x + b*x^2 + c*x^3 = (P, Q*v) for x = r + v,
//   P = a*r + b*(r^2-n^2) + c*r*(r^2-3n^2)
//   Q = a + 2*b*r + c*(3r^2-n^2),  n^2=|v|^2,  |upd|^2 = P^2 + Q^2 n^2
//
// Round 3: force 64 regs (__launch_bounds__(256,4)) for ~48% occupancy,
// fold the GELU 0.5 into the W2 tables (h' = z + z*tanh(u), W2' = W2/2),
// 256-thread blocks. Still 4 octonions/thread as two f32x2 streams with
// 3x LDS.128 weight fetch per MLP iter, imaginaries staged in shared.
// ---------------------------------------------------------------------------

typedef unsigned long long U64;

__device__ __forceinline__ U64 pk2(float lo, float hi) {
    U64 r; asm("mov.b64 %0, {%1, %2};" : "=l"(r) : "f"(lo), "f"(hi)); return r;
}
__device__ __forceinline__ void upk2(U64 v, float& lo, float& hi) {
    asm("mov.b64 {%0, %1}, %2;" : "=f"(lo), "=f"(hi) : "l"(v));
}
__device__ __forceinline__ U64 fma2(U64 a, U64 b, U64 c) {
    U64 d; asm("fma.rn.f32x2 %0, %1, %2, %3;" : "=l"(d) : "l"(a), "l"(b), "l"(c)); return d;
}
__device__ __forceinline__ U64 mul2(U64 a, U64 b) {
    U64 d; asm("mul.rn.f32x2 %0, %1, %2;" : "=l"(d) : "l"(a), "l"(b)); return d;
}
__device__ __forceinline__ U64 add2(U64 a, U64 b) {
    U64 d; asm("add.rn.f32x2 %0, %1, %2;" : "=l"(d) : "l"(a), "l"(b)); return d;
}
__device__ __forceinline__ float tanh_ap(float x) {
    float t; asm("tanh.approx.f32 %0, %1;" : "=f"(t) : "f"(x)); return t;
}
__device__ __forceinline__ float sqrt_ap(float x) {
    float t; asm("sqrt.approx.f32 %0, %1;" : "=f"(t) : "f"(x)); return t;
}
__device__ __forceinline__ float rsqrt_ap(float x) {
    float t; asm("rsqrt.approx.f32 %0, %1;" : "=f"(t) : "f"(x)); return t;
}

#define TPB 256          // threads per block
#define OPB 1024         // octonions per block (4 per thread)
#define SLOT 15          // U64 stride per thread in staging buffer (conflict-free 64b)

struct Oct2 {            // one f32x2 stream = 2 octonions packed lane-wise
    U64 p0, n2, np;
};

__global__ __launch_bounds__(TPB, 4)
void g2ff_kernel(const float4* __restrict__ in4,
                 const float*  __restrict__ W1,   // (32,2) row-major
                 const float*  __restrict__ b1,   // (32)
                 const float*  __restrict__ W2,   // (3,32) row-major
                 const float*  __restrict__ b2,   // (3)
                 const float*  __restrict__ alpha,
                 float4*       __restrict__ out4)
{
    __shared__ ulonglong2 sW1[32];   // (w0,w0 | w1,w1)
    __shared__ ulonglong2 sBW[32];   // (b1,b1 | 0.5*w2c,0.5*w2c)
    __shared__ ulonglong2 sW2[32];   // (0.5*w2a,.. | 0.5*w2b,..)
    __shared__ U64        sB2[3];
    __shared__ float      sScal[2];
    __shared__ U64        sImag[TPB * SLOT];   // 14 U64 used per thread

    const int t = threadIdx.x;
    if (t < 32) {
        float w0 = W1[2 * t], w1 = W1[2 * t + 1];
        ulonglong2 q; q.x = pk2(w0, w0); q.y = pk2(w1, w1);
        sW1[t] = q;
        float bb = b1[t], wc = 0.5f * W2[64 + t];
        ulonglong2 qb; qb.x = pk2(bb, bb); qb.y = pk2(wc, wc);
        sBW[t] = qb;
        float wa = 0.5f * W2[t], wb = 0.5f * W2[32 + t];
        ulonglong2 q2; q2.x = pk2(wa, wa); q2.y = pk2(wb, wb);
        sW2[t] = q2;
    } else if (t == 32) {
        float al  = alpha[0];
        float lam = 1.0f / (1.0f + __expf(-al));
        sScal[0] = lam;
        sScal[1] = 1.0f - lam;
        sB2[0] = pk2(b2[0], b2[0]);
        sB2[1] = pk2(b2[1], b2[1]);
        sB2[2] = pk2(b2[2], b2[2]);
    }
    __syncthreads();

    const int base = blockIdx.x * OPB;
    const int mA = base + t;
    const int mB = base + TPB + t;
    const int mC = base + 2 * TPB + t;
    const int mD = base + 3 * TPB + t;

    U64* myImag = &sImag[t * SLOT];

    Oct2 X, Y;

    // ---- load + pack + n^2 + stage imaginaries, stream X ----
    {
        float4 A0 = in4[2 * mA + 0];
        float4 A1 = in4[2 * mA + 1];
        float4 B0 = in4[2 * mB + 0];
        float4 B1 = in4[2 * mB + 1];
        X.p0 = pk2(A0.x, B0.x);
        U64 p1 = pk2(A0.y, B0.y);
        U64 p2 = pk2(A0.z, B0.z);
        U64 p3 = pk2(A0.w, B0.w);
        U64 p4 = pk2(A1.x, B1.x);
        U64 p5 = pk2(A1.y, B1.y);
        U64 p6 = pk2(A1.z, B1.z);
        U64 p7 = pk2(A1.w, B1.w);
        U64 n2 = mul2(p1, p1);
        n2 = fma2(p2, p2, n2);
        n2 = fma2(p3, p3, n2);
        n2 = fma2(p4, p4, n2);
        n2 = fma2(p5, p5, n2);
        n2 = fma2(p6, p6, n2);
        n2 = fma2(p7, p7, n2);
        X.n2 = n2;
        float nl, nh; upk2(n2, nl, nh);
        X.np = pk2(sqrt_ap(nl), sqrt_ap(nh));
        myImag[0] = p1; myImag[1] = p2; myImag[2] = p3; myImag[3] = p4;
        myImag[4] = p5; myImag[5] = p6; myImag[6] = p7;
    }
    // ---- stream Y ----
    {
        float4 A0 = in4[2 * mC + 0];
        float4 A1 = in4[2 * mC + 1];
        float4 B0 = in4[2 * mD + 0];
        float4 B1 = in4[2 * mD + 1];
        Y.p0 = pk2(A0.x, B0.x);
        U64 p1 = pk2(A0.y, B0.y);
        U64 p2 = pk2(A0.z, B0.z);
        U64 p3 = pk2(A0.w, B0.w);
        U64 p4 = pk2(A1.x, B1.x);
        U64 p5 = pk2(A1.y, B1.y);
        U64 p6 = pk2(A1.z, B1.z);
        U64 p7 = pk2(A1.w, B1.w);
        U64 n2 = mul2(p1, p1);
        n2 = fma2(p2, p2, n2);
        n2 = fma2(p3, p3, n2);
        n2 = fma2(p4, p4, n2);
        n2 = fma2(p5, p5, n2);
        n2 = fma2(p6, p6, n2);
        n2 = fma2(p7, p7, n2);
        Y.n2 = n2;
        float nl, nh; upk2(n2, nl, nh);
        Y.np = pk2(sqrt_ap(nl), sqrt_ap(nh));
        myImag[7]  = p1; myImag[8]  = p2; myImag[9]  = p3; myImag[10] = p4;
        myImag[11] = p5; myImag[12] = p6; myImag[13] = p7;
    }

    // GELU-tanh constants
    const U64 C1 = pk2(0.7978845608028654f, 0.7978845608028654f);
    const U64 C2 = pk2(0.035677408136300125f, 0.035677408136300125f);

    U64 aAX = sB2[0], aBX = sB2[1], aCX = sB2[2];
    U64 aAY = sB2[0], aBY = sB2[1], aCY = sB2[2];

#pragma unroll
    for (int j = 0; j < 32; j++) {
        ulonglong2 w1j = sW1[j];     // LDS.128 broadcast
        ulonglong2 bwj = sBW[j];     // LDS.128 broadcast
        ulonglong2 w2j = sW2[j];     // LDS.128 broadcast

        // stream X:  h' = z*(1+tanh(u)) = 2*gelu(z); W2 tables pre-halved
        {
            U64 z  = fma2(X.np, w1j.y, fma2(X.p0, w1j.x, bwj.x));
            U64 z2 = mul2(z, z);
            U64 q  = fma2(z2, C2, C1);
            U64 u  = mul2(z, q);
            float ul, uh; upk2(u, ul, uh);
            U64 tt = pk2(tanh_ap(ul), tanh_ap(uh));
            U64 h  = fma2(z, tt, z);
            aAX = fma2(h, w2j.x, aAX);
            aBX = fma2(h, w2j.y, aBX);
            aCX = fma2(h, bwj.y, aCX);
        }
        // stream Y
        {
            U64 z  = fma2(Y.np, w1j.y, fma2(Y.p0, w1j.x, bwj.x));
            U64 z2 = mul2(z, z);
            U64 q  = fma2(z2, C2, C1);
            U64 u  = mul2(z, q);
            float ul, uh; upk2(u, ul, uh);
            U64 tt = pk2(tanh_ap(ul), tanh_ap(uh));
            U64 h  = fma2(z, tt, z);
            aAY = fma2(h, w2j.x, aAY);
            aBY = fma2(h, w2j.y, aBY);
            aCY = fma2(h, bwj.y, aCY);
        }
    }

    const U64 N1  = pk2(-1.0f, -1.0f);
    const U64 N3  = pk2(-3.0f, -3.0f);
    const U64 TWO = pk2(2.0f, 2.0f);

    const float lam = sScal[0], oml = sScal[1];
    const U64 LAM = pk2(lam, lam);
    const U64 OML = pk2(oml, oml);

    // ---- epilogue stream X ----
    {
        U64 r2 = mul2(X.p0, X.p0);
        U64 s2 = fma2(X.n2, N1, r2);
        U64 u3 = fma2(X.n2, N3, r2);
        U64 s3 = mul2(X.p0, u3);
        U64 t3 = fma2(r2, TWO, s2);
        U64 P  = fma2(aAX, X.p0, fma2(aBX, s2, mul2(aCX, s3)));
        U64 tr = add2(X.p0, X.p0);
        U64 Q  = fma2(aCX, t3, fma2(aBX, tr, aAX));
        U64 ss = fma2(mul2(Q, Q), X.n2, mul2(P, P));
        float sl, sh; upk2(ss, sl, sh);
        sl = fmaxf(sl, 1e-16f);
        sh = fmaxf(sh, 1e-16f);
        U64 inv = pk2(rsqrt_ap(sl), rsqrt_ap(sh));
        U64 li = mul2(LAM, inv);
        U64 K  = fma2(li, Q, OML);
        U64 o0 = fma2(li, P, mul2(X.p0, OML));

        U64 o1 = mul2(myImag[0], K);
        U64 o2 = mul2(myImag[1], K);
        U64 o3 = mul2(myImag[2], K);
        U64 o4 = mul2(myImag[3], K);
        U64 o5 = mul2(myImag[4], K);
        U64 o6 = mul2(myImag[5], K);
        U64 o7 = mul2(myImag[6], K);

        float4 OA0, OA1, OB0, OB1;
        upk2(o0, OA0.x, OB0.x);
        upk2(o1, OA0.y, OB0.y);
        upk2(o2, OA0.z, OB0.z);
        upk2(o3, OA0.w, OB0.w);
        upk2(o4, OA1.x, OB1.x);
        upk2(o5, OA1.y, OB1.y);
        upk2(o6, OA1.z, OB1.z);
        upk2(o7, OA1.w, OB1.w);
        out4[2 * mA + 0] = OA0;
        out4[2 * mA + 1] = OA1;
        out4[2 * mB + 0] = OB0;
        out4[2 * mB + 1] = OB1;
    }
    // ---- epilogue stream Y ----
    {
        U64 r2 = mul2(Y.p0, Y.p0);
        U64 s2 = fma2(Y.n2, N1, r2);
        U64 u3 = fma2(Y.n2, N3, r2);
        U64 s3 = mul2(Y.p0, u3);
        U64 t3 = fma2(r2, TWO, s2);
        U64 P  = fma2(aAY, Y.p0, fma2(aBY, s2, mul2(aCY, s3)));
        U64 tr = add2(Y.p0, Y.p0);
        U64 Q  = fma2(aCY, t3, fma2(aBY, tr, aAY));
        U64 ss = fma2(mul2(Q, Q), Y.n2, mul2(P, P));
        float sl, sh; upk2(ss, sl, sh);
        sl = fmaxf(sl, 1e-16f);
        sh = fmaxf(sh, 1e-16f);
        U64 inv = pk2(rsqrt_ap(sl), rsqrt_ap(sh));
        U64 li = mul2(LAM, inv);
        U64 K  = fma2(li, Q, OML);
        U64 o0 = fma2(li, P, mul2(Y.p0, OML));

        U64 o1 = mul2(myImag[7],  K);
        U64 o2 = mul2(myImag[8],  K);
        U64 o3 = mul2(myImag[9],  K);
        U64 o4 = mul2(myImag[10], K);
        U64 o5 = mul2(myImag[11], K);
        U64 o6 = mul2(myImag[12], K);
        U64 o7 = mul2(myImag[13], K);

        float4 OA0, OA1, OB0, OB1;
        upk2(o0, OA0.x, OB0.x);
        upk2(o1, OA0.y, OB0.y);
        upk2(o2, OA0.z, OB0.z);
        upk2(o3, OA0.w, OB0.w);
        upk2(o4, OA1.x, OB1.x);
        upk2(o5, OA1.y, OB1.y);
        upk2(o6, OA1.z, OB1.z);
        upk2(o7, OA1.w, OB1.w);
        out4[2 * mC + 0] = OA0;
        out4[2 * mC + 1] = OA1;
        out4[2 * mD + 0] = OB0;
        out4[2 * mD + 1] = OB1;
    }
}

extern "C" void kernel_launch(void* const* d_in, const int* in_sizes, int n_in,
                              void* d_out, int out_size)
{
    const float* o     = (const float*)d_in[0];
    const float* W1    = (const float*)d_in[1];
    const float* b1    = (const float*)d_in[2];
    const float* W2    = (const float*)d_in[3];
    const float* b2    = (const float*)d_in[4];
    const float* alpha = (const float*)d_in[5];

    const int total = in_sizes[0];          // 33,554,432 floats
    const int octs  = total / 8;            // 4,194,304 octonions
    const int blocks = octs / OPB;          // 4096

    g2ff_kernel<<<blocks, TPB>>>((const float4*)o, W1, b1, W2, b2, alpha,
                                 (float4*)d_out);
}

// round 4
// speedup vs baseline: 1.0378x; 1.0378x over previous
#include <cuda_runtime.h>
#include <cuda_bf16.h>

// ---------------------------------------------------------------------------
// G2EquivariantFeedForward, GB300 sm_103a — round 4
//
// Closed form: upd = a*x + b*x^2 + c*x^3 = (P, Q*v) for x = r + v,
//   P = a*r + b*(r^2-n^2) + c*r*(r^2-3n^2)
//   Q = a + 2*b*r + c*(3r^2-n^2),  n^2=|v|^2,  |upd|^2 = P^2 + Q^2 n^2
//
// Round 4: shrink loop-live registers so the 64-reg cap fits WITHOUT spills
// (round 3 clamped 79->64 and spilled, regressing):
//   - n2 dropped from loop state; epilogue recomputes n2 = np*np
//   - halved-W2 GELU fold kept (h' = z + z*tanh(u), W2' = W2/2)
//   - 128-thread blocks, __launch_bounds__(128, 8) -> 1024 thr/SM target
// Still 4 octonions/thread as two f32x2 streams, 3x LDS.128 weights/iter,
// imaginaries staged in conflict-free shared (stride 15 U64).
// ---------------------------------------------------------------------------

typedef unsigned long long U64;

__device__ __forceinline__ U64 pk2(float lo, float hi) {
    U64 r; asm("mov.b64 %0, {%1, %2};" : "=l"(r) : "f"(lo), "f"(hi)); return r;
}
__device__ __forceinline__ void upk2(U64 v, float& lo, float& hi) {
    asm("mov.b64 {%0, %1}, %2;" : "=f"(lo), "=f"(hi) : "l"(v));
}
__device__ __forceinline__ U64 fma2(U64 a, U64 b, U64 c) {
    U64 d; asm("fma.rn.f32x2 %0, %1, %2, %3;" : "=l"(d) : "l"(a), "l"(b), "l"(c)); return d;
}
__device__ __forceinline__ U64 mul2(U64 a, U64 b) {
    U64 d; asm("mul.rn.f32x2 %0, %1, %2;" : "=l"(d) : "l"(a), "l"(b)); return d;
}
__device__ __forceinline__ U64 add2(U64 a, U64 b) {
    U64 d; asm("add.rn.f32x2 %0, %1, %2;" : "=l"(d) : "l"(a), "l"(b)); return d;
}
__device__ __forceinline__ float tanh_ap(float x) {
    float t; asm("tanh.approx.f32 %0, %1;" : "=f"(t) : "f"(x)); return t;
}
__device__ __forceinline__ float sqrt_ap(float x) {
    float t; asm("sqrt.approx.f32 %0, %1;" : "=f"(t) : "f"(x)); return t;
}
__device__ __forceinline__ float rsqrt_ap(float x) {
    float t; asm("rsqrt.approx.f32 %0, %1;" : "=f"(t) : "f"(x)); return t;
}

#define TPB 128          // threads per block
#define OPB 512          // octonions per block (4 per thread)
#define SLOT 15          // U64 stride per thread in staging buffer (conflict-free 64b)

__global__ __launch_bounds__(TPB, 8)
void g2ff_kernel(const float4* __restrict__ in4,
                 const float*  __restrict__ W1,   // (32,2) row-major
                 const float*  __restrict__ b1,   // (32)
                 const float*  __restrict__ W2,   // (3,32) row-major
                 const float*  __restrict__ b2,   // (3)
                 const float*  __restrict__ alpha,
                 float4*       __restrict__ out4)
{
    __shared__ ulonglong2 sW1[32];   // (w0,w0 | w1,w1)
    __shared__ ulonglong2 sBW[32];   // (b1,b1 | 0.5*w2c,0.5*w2c)
    __shared__ ulonglong2 sW2[32];   // (0.5*w2a,.. | 0.5*w2b,..)
    __shared__ U64        sB2[3];
    __shared__ float      sScal[2];
    __shared__ U64        sImag[TPB * SLOT];   // 14 U64 used per thread

    const int t = threadIdx.x;
    if (t < 32) {
        float w0 = W1[2 * t], w1 = W1[2 * t + 1];
        ulonglong2 q; q.x = pk2(w0, w0); q.y = pk2(w1, w1);
        sW1[t] = q;
        float bb = b1[t], wc = 0.5f * W2[64 + t];
        ulonglong2 qb; qb.x = pk2(bb, bb); qb.y = pk2(wc, wc);
        sBW[t] = qb;
        float wa = 0.5f * W2[t], wb = 0.5f * W2[32 + t];
        ulonglong2 q2; q2.x = pk2(wa, wa); q2.y = pk2(wb, wb);
        sW2[t] = q2;
    } else if (t == 32) {
        float al  = alpha[0];
        float lam = 1.0f / (1.0f + __expf(-al));
        sScal[0] = lam;
        sScal[1] = 1.0f - lam;
        sB2[0] = pk2(b2[0], b2[0]);
        sB2[1] = pk2(b2[1], b2[1]);
        sB2[2] = pk2(b2[2], b2[2]);
    }
    __syncthreads();

    const int base = blockIdx.x * OPB;
    const int mA = base + t;
    const int mB = base + TPB + t;
    const int mC = base + 2 * TPB + t;
    const int mD = base + 3 * TPB + t;

    U64* myImag = &sImag[t * SLOT];

    // Loop-live state per stream: p0, np only (n2 recomputed in epilogue).
    U64 Xp0, Xnp, Yp0, Ynp;

    // ---- load + pack + n^2 + stage imaginaries, stream X ----
    {
        float4 A0 = in4[2 * mA + 0];
        float4 A1 = in4[2 * mA + 1];
        float4 B0 = in4[2 * mB + 0];
        float4 B1 = in4[2 * mB + 1];
        Xp0 = pk2(A0.x, B0.x);
        U64 p1 = pk2(A0.y, B0.y);
        U64 p2 = pk2(A0.z, B0.z);
        U64 p3 = pk2(A0.w, B0.w);
        U64 p4 = pk2(A1.x, B1.x);
        U64 p5 = pk2(A1.y, B1.y);
        U64 p6 = pk2(A1.z, B1.z);
        U64 p7 = pk2(A1.w, B1.w);
        U64 n2 = mul2(p1, p1);
        n2 = fma2(p2, p2, n2);
        n2 = fma2(p3, p3, n2);
        n2 = fma2(p4, p4, n2);
        n2 = fma2(p5, p5, n2);
        n2 = fma2(p6, p6, n2);
        n2 = fma2(p7, p7, n2);
        float nl, nh; upk2(n2, nl, nh);
        Xnp = pk2(sqrt_ap(nl), sqrt_ap(nh));
        myImag[0] = p1; myImag[1] = p2; myImag[2] = p3; myImag[3] = p4;
        myImag[4] = p5; myImag[5] = p6; myImag[6] = p7;
    }
    // ---- stream Y ----
    {
        float4 A0 = in4[2 * mC + 0];
        float4 A1 = in4[2 * mC + 1];
        float4 B0 = in4[2 * mD + 0];
        float4 B1 = in4[2 * mD + 1];
        Yp0 = pk2(A0.x, B0.x);
        U64 p1 = pk2(A0.y, B0.y);
        U64 p2 = pk2(A0.z, B0.z);
        U64 p3 = pk2(A0.w, B0.w);
        U64 p4 = pk2(A1.x, B1.x);
        U64 p5 = pk2(A1.y, B1.y);
        U64 p6 = pk2(A1.z, B1.z);
        U64 p7 = pk2(A1.w, B1.w);
        U64 n2 = mul2(p1, p1);
        n2 = fma2(p2, p2, n2);
        n2 = fma2(p3, p3, n2);
        n2 = fma2(p4, p4, n2);
        n2 = fma2(p5, p5, n2);
        n2 = fma2(p6, p6, n2);
        n2 = fma2(p7, p7, n2);
        float nl, nh; upk2(n2, nl, nh);
        Ynp = pk2(sqrt_ap(nl), sqrt_ap(nh));
        myImag[7]  = p1; myImag[8]  = p2; myImag[9]  = p3; myImag[10] = p4;
        myImag[11] = p5; myImag[12] = p6; myImag[13] = p7;
    }

    // GELU-tanh constants
    const U64 C1 = pk2(0.7978845608028654f, 0.7978845608028654f);
    const U64 C2 = pk2(0.035677408136300125f, 0.035677408136300125f);

    U64 aAX = sB2[0], aBX = sB2[1], aCX = sB2[2];
    U64 aAY = sB2[0], aBY = sB2[1], aCY = sB2[2];

#pragma unroll
    for (int j = 0; j < 32; j++) {
        ulonglong2 w1j = sW1[j];     // LDS.128 broadcast
        ulonglong2 bwj = sBW[j];     // LDS.128 broadcast
        ulonglong2 w2j = sW2[j];     // LDS.128 broadcast

        // stream X:  h' = z*(1+tanh(u)) = 2*gelu(z); W2 tables pre-halved
        {
            U64 z  = fma2(Xnp, w1j.y, fma2(Xp0, w1j.x, bwj.x));
            U64 z2 = mul2(z, z);
            U64 q  = fma2(z2, C2, C1);
            U64 u  = mul2(z, q);
            float ul, uh; upk2(u, ul, uh);
            U64 tt = pk2(tanh_ap(ul), tanh_ap(uh));
            U64 h  = fma2(z, tt, z);
            aAX = fma2(h, w2j.x, aAX);
            aBX = fma2(h, w2j.y, aBX);
            aCX = fma2(h, bwj.y, aCX);
        }
        // stream Y
        {
            U64 z  = fma2(Ynp, w1j.y, fma2(Yp0, w1j.x, bwj.x));
            U64 z2 = mul2(z, z);
            U64 q  = fma2(z2, C2, C1);
            U64 u  = mul2(z, q);
            float ul, uh; upk2(u, ul, uh);
            U64 tt = pk2(tanh_ap(ul), tanh_ap(uh));
            U64 h  = fma2(z, tt, z);
            aAY = fma2(h, w2j.x, aAY);
            aBY = fma2(h, w2j.y, aBY);
            aCY = fma2(h, bwj.y, aCY);
        }
    }

    const U64 N1  = pk2(-1.0f, -1.0f);
    const U64 N3  = pk2(-3.0f, -3.0f);
    const U64 TWO = pk2(2.0f, 2.0f);

    const float lam = sScal[0], oml = sScal[1];
    const U64 LAM = pk2(lam, lam);
    const U64 OML = pk2(oml, oml);

    // ---- epilogue stream X ----
    {
        U64 n2 = mul2(Xnp, Xnp);              // recompute (np = sqrt(n2))
        U64 r2 = mul2(Xp0, Xp0);
        U64 s2 = fma2(n2, N1, r2);
        U64 u3 = fma2(n2, N3, r2);
        U64 s3 = mul2(Xp0, u3);
        U64 t3 = fma2(r2, TWO, s2);
        U64 P  = fma2(aAX, Xp0, fma2(aBX, s2, mul2(aCX, s3)));
        U64 tr = add2(Xp0, Xp0);
        U64 Q  = fma2(aCX, t3, fma2(aBX, tr, aAX));
        U64 ss = fma2(mul2(Q, Q), n2, mul2(P, P));
        float sl, sh; upk2(ss, sl, sh);
        sl = fmaxf(sl, 1e-16f);
        sh = fmaxf(sh, 1e-16f);
        U64 inv = pk2(rsqrt_ap(sl), rsqrt_ap(sh));
        U64 li = mul2(LAM, inv);
        U64 K  = fma2(li, Q, OML);
        U64 o0 = fma2(li, P, mul2(Xp0, OML));

        U64 o1 = mul2(myImag[0], K);
        U64 o2 = mul2(myImag[1], K);
        U64 o3 = mul2(myImag[2], K);
        U64 o4 = mul2(myImag[3], K);
        U64 o5 = mul2(myImag[4], K);
        U64 o6 = mul2(myImag[5], K);
        U64 o7 = mul2(myImag[6], K);

        float4 OA0, OA1, OB0, OB1;
        upk2(o0, OA0.x, OB0.x);
        upk2(o1, OA0.y, OB0.y);
        upk2(o2, OA0.z, OB0.z);
        upk2(o3, OA0.w, OB0.w);
        upk2(o4, OA1.x, OB1.x);
        upk2(o5, OA1.y, OB1.y);
        upk2(o6, OA1.z, OB1.z);
        upk2(o7, OA1.w, OB1.w);
        out4[2 * mA + 0] = OA0;
        out4[2 * mA + 1] = OA1;
        out4[2 * mB + 0] = OB0;
        out4[2 * mB + 1] = OB1;
    }
    // ---- epilogue stream Y ----
    {
        U64 n2 = mul2(Ynp, Ynp);
        U64 r2 = mul2(Yp0, Yp0);
        U64 s2 = fma2(n2, N1, r2);
        U64 u3 = fma2(n2, N3, r2);
        U64 s3 = mul2(Yp0, u3);
        U64 t3 = fma2(r2, TWO, s2);
        U64 P  = fma2(aAY, Yp0, fma2(aBY, s2, mul2(aCY, s3)));
        U64 tr = add2(Yp0, Yp0);
        U64 Q  = fma2(aCY, t3, fma2(aBY, tr, aAY));
        U64 ss = fma2(mul2(Q, Q), n2, mul2(P, P));
        float sl, sh; upk2(ss, sl, sh);
        sl = fmaxf(sl, 1e-16f);
        sh = fmaxf(sh, 1e-16f);
        U64 inv = pk2(rsqrt_ap(sl), rsqrt_ap(sh));
        U64 li = mul2(LAM, inv);
        U64 K  = fma2(li, Q, OML);
        U64 o0 = fma2(li, P, mul2(Yp0, OML));

        U64 o1 = mul2(myImag[7],  K);
        U64 o2 = mul2(myImag[8],  K);
        U64 o3 = mul2(myImag[9],  K);
        U64 o4 = mul2(myImag[10], K);
        U64 o5 = mul2(myImag[11], K);
        U64 o6 = mul2(myImag[12], K);
        U64 o7 = mul2(myImag[13], K);

        float4 OA0, OA1, OB0, OB1;
        upk2(o0, OA0.x, OB0.x);
        upk2(o1, OA0.y, OB0.y);
        upk2(o2, OA0.z, OB0.z);
        upk2(o3, OA0.w, OB0.w);
        upk2(o4, OA1.x, OB1.x);
        upk2(o5, OA1.y, OB1.y);
        upk2(o6, OA1.z, OB1.z);
        upk2(o7, OA1.w, OB1.w);
        out4[2 * mC + 0] = OA0;
        out4[2 * mC + 1] = OA1;
        out4[2 * mD + 0] = OB0;
        out4[2 * mD + 1] = OB1;
    }
}

extern "C" void kernel_launch(void* const* d_in, const int* in_sizes, int n_in,
                              void* d_out, int out_size)
{
    const float* o     = (const float*)d_in[0];
    const float* W1    = (const float*)d_in[1];
    const float* b1    = (const float*)d_in[2];
    const float* W2    = (const float*)d_in[3];
    const float* b2    = (const float*)d_in[4];
    const float* alpha = (const float*)d_in[5];

    const int total = in_sizes[0];          // 33,554,432 floats
    const int octs  = total / 8;            // 4,194,304 octonions
    const int blocks = octs / OPB;          // 8192

    g2ff_kernel<<<blocks, TPB>>>((const float4*)o, W1, b1, W2, b2, alpha,
                                 (float4*)d_out);
}

// round 5
// speedup vs baseline: 1.1453x; 1.1037x over previous
#include <cuda_runtime.h>
#include <cuda_bf16.h>

// ---------------------------------------------------------------------------
// G2EquivariantFeedForward, GB300 sm_103a — round 5
//
// Closed form: upd = a*x + b*x^2 + c*x^3 = (P, Q*v) for x = r + v,
//   P = a*r + b*(r^2-n^2) + c*r*(r^2-3n^2)
//   Q = a + 2*b*r + c*(3r^2-n^2),  n^2=|v|^2,  |upd|^2 = P^2 + Q^2 n^2
//
// Round 5: issue-slot diet.
//  - imaginaries NEVER packed/staged: n^2 computed scalar from float4 loads;
//    epilogue RE-LOADS the octonion from global (L2 hit) and scales scalar
//    components by unpacked K. Deletes all STS/LDS staging + ~200 ALU movs.
//  - only (r,r') and (n,n') packed as f32x2 for the 32-iter MLP loop.
//  - halved-W2 GELU fold (h' = z + z*tanh(u), W2' = W2/2), tanh.approx.
//  - 4 octonions/thread as two f32x2 streams, 3x LDS.128 weights/iter.
// ---------------------------------------------------------------------------

typedef unsigned long long U64;

__device__ __forceinline__ U64 pk2(float lo, float hi) {
    U64 r; asm("mov.b64 %0, {%1, %2};" : "=l"(r) : "f"(lo), "f"(hi)); return r;
}
__device__ __forceinline__ void upk2(U64 v, float& lo, float& hi) {
    asm("mov.b64 {%0, %1}, %2;" : "=f"(lo), "=f"(hi) : "l"(v));
}
__device__ __forceinline__ U64 fma2(U64 a, U64 b, U64 c) {
    U64 d; asm("fma.rn.f32x2 %0, %1, %2, %3;" : "=l"(d) : "l"(a), "l"(b), "l"(c)); return d;
}
__device__ __forceinline__ U64 mul2(U64 a, U64 b) {
    U64 d; asm("mul.rn.f32x2 %0, %1, %2;" : "=l"(d) : "l"(a), "l"(b)); return d;
}
__device__ __forceinline__ U64 add2(U64 a, U64 b) {
    U64 d; asm("add.rn.f32x2 %0, %1, %2;" : "=l"(d) : "l"(a), "l"(b)); return d;
}
__device__ __forceinline__ float tanh_ap(float x) {
    float t; asm("tanh.approx.f32 %0, %1;" : "=f"(t) : "f"(x)); return t;
}
__device__ __forceinline__ float sqrt_ap(float x) {
    float t; asm("sqrt.approx.f32 %0, %1;" : "=f"(t) : "f"(x)); return t;
}
__device__ __forceinline__ float rsqrt_ap(float x) {
    float t; asm("rsqrt.approx.f32 %0, %1;" : "=f"(t) : "f"(x)); return t;
}

__device__ __forceinline__ float norm2_imag(const float4& a0, const float4& a1) {
    float n = a0.y * a0.y;
    n = fmaf(a0.z, a0.z, n);
    n = fmaf(a0.w, a0.w, n);
    n = fmaf(a1.x, a1.x, n);
    n = fmaf(a1.y, a1.y, n);
    n = fmaf(a1.z, a1.z, n);
    n = fmaf(a1.w, a1.w, n);
    return n;
}

#define TPB 128          // threads per block
#define OPB 512          // octonions per block (4 per thread)

__global__ __launch_bounds__(TPB, 8)
void g2ff_kernel(const float4* __restrict__ in4,
                 const float*  __restrict__ W1,   // (32,2) row-major
                 const float*  __restrict__ b1,   // (32)
                 const float*  __restrict__ W2,   // (3,32) row-major
                 const float*  __restrict__ b2,   // (3)
                 const float*  __restrict__ alpha,
                 float4*       __restrict__ out4)
{
    __shared__ ulonglong2 sW1[32];   // (w0,w0 | w1,w1)
    __shared__ ulonglong2 sBW[32];   // (b1,b1 | 0.5*w2c,0.5*w2c)
    __shared__ ulonglong2 sW2[32];   // (0.5*w2a,.. | 0.5*w2b,..)
    __shared__ U64        sB2[3];
    __shared__ float      sScal[2];

    const int t = threadIdx.x;
    if (t < 32) {
        float w0 = W1[2 * t], w1 = W1[2 * t + 1];
        ulonglong2 q; q.x = pk2(w0, w0); q.y = pk2(w1, w1);
        sW1[t] = q;
        float bb = b1[t], wc = 0.5f * W2[64 + t];
        ulonglong2 qb; qb.x = pk2(bb, bb); qb.y = pk2(wc, wc);
        sBW[t] = qb;
        float wa = 0.5f * W2[t], wb = 0.5f * W2[32 + t];
        ulonglong2 q2; q2.x = pk2(wa, wa); q2.y = pk2(wb, wb);
        sW2[t] = q2;
    } else if (t == 32) {
        float al  = alpha[0];
        float lam = 1.0f / (1.0f + __expf(-al));
        sScal[0] = lam;
        sScal[1] = 1.0f - lam;
        sB2[0] = pk2(b2[0], b2[0]);
        sB2[1] = pk2(b2[1], b2[1]);
        sB2[2] = pk2(b2[2], b2[2]);
    }
    __syncthreads();

    const int base = blockIdx.x * OPB;
    const int mA = base + t;
    const int mB = base + TPB + t;
    const int mC = base + 2 * TPB + t;
    const int mD = base + 3 * TPB + t;

    // ---- prologue: scalar n^2 per octonion; pack only (r, np) pairs ----
    U64 Xp0, Xnp, Yp0, Ynp;
    {
        float4 a0 = in4[2 * mA + 0];
        float4 a1 = in4[2 * mA + 1];
        float4 b0 = in4[2 * mB + 0];
        float4 b1v = in4[2 * mB + 1];
        float nA = norm2_imag(a0, a1);
        float nB = norm2_imag(b0, b1v);
        Xp0 = pk2(a0.x, b0.x);
        Xnp = pk2(sqrt_ap(nA), sqrt_ap(nB));
    }
    {
        float4 a0 = in4[2 * mC + 0];
        float4 a1 = in4[2 * mC + 1];
        float4 b0 = in4[2 * mD + 0];
        float4 b1v = in4[2 * mD + 1];
        float nA = norm2_imag(a0, a1);
        float nB = norm2_imag(b0, b1v);
        Yp0 = pk2(a0.x, b0.x);
        Ynp = pk2(sqrt_ap(nA), sqrt_ap(nB));
    }

    // GELU-tanh constants
    const U64 C1 = pk2(0.7978845608028654f, 0.7978845608028654f);
    const U64 C2 = pk2(0.035677408136300125f, 0.035677408136300125f);

    U64 aAX = sB2[0], aBX = sB2[1], aCX = sB2[2];
    U64 aAY = sB2[0], aBY = sB2[1], aCY = sB2[2];

#pragma unroll
    for (int j = 0; j < 32; j++) {
        ulonglong2 w1j = sW1[j];     // LDS.128 broadcast
        ulonglong2 bwj = sBW[j];     // LDS.128 broadcast
        ulonglong2 w2j = sW2[j];     // LDS.128 broadcast

        // stream X:  h' = z*(1+tanh(u)) = 2*gelu(z); W2 tables pre-halved
        {
            U64 z  = fma2(Xnp, w1j.y, fma2(Xp0, w1j.x, bwj.x));
            U64 z2 = mul2(z, z);
            U64 q  = fma2(z2, C2, C1);
            U64 u  = mul2(z, q);
            float ul, uh; upk2(u, ul, uh);
            U64 tt = pk2(tanh_ap(ul), tanh_ap(uh));
            U64 h  = fma2(z, tt, z);
            aAX = fma2(h, w2j.x, aAX);
            aBX = fma2(h, w2j.y, aBX);
            aCX = fma2(h, bwj.y, aCX);
        }
        // stream Y
        {
            U64 z  = fma2(Ynp, w1j.y, fma2(Yp0, w1j.x, bwj.x));
            U64 z2 = mul2(z, z);
            U64 q  = fma2(z2, C2, C1);
            U64 u  = mul2(z, q);
            float ul, uh; upk2(u, ul, uh);
            U64 tt = pk2(tanh_ap(ul), tanh_ap(uh));
            U64 h  = fma2(z, tt, z);
            aAY = fma2(h, w2j.x, aAY);
            aBY = fma2(h, w2j.y, aBY);
            aCY = fma2(h, bwj.y, aCY);
        }
    }

    const U64 N1  = pk2(-1.0f, -1.0f);
    const U64 N3  = pk2(-3.0f, -3.0f);
    const U64 TWO = pk2(2.0f, 2.0f);

    const float lam = sScal[0], oml = sScal[1];
    const U64 LAM = pk2(lam, lam);
    const U64 OML = pk2(oml, oml);

    // ---- epilogue stream X (re-load octonions from global; L2 hit) ----
    {
        U64 n2 = mul2(Xnp, Xnp);              // recompute (np = sqrt(n2))
        U64 r2 = mul2(Xp0, Xp0);
        U64 s2 = fma2(n2, N1, r2);            // r^2 - n^2
        U64 u3 = fma2(n2, N3, r2);            // r^2 - 3n^2
        U64 s3 = mul2(Xp0, u3);
        U64 t3 = fma2(r2, TWO, s2);           // 3r^2 - n^2
        U64 P  = fma2(aAX, Xp0, fma2(aBX, s2, mul2(aCX, s3)));
        U64 tr = add2(Xp0, Xp0);
        U64 Q  = fma2(aCX, t3, fma2(aBX, tr, aAX));
        U64 ss = fma2(mul2(Q, Q), n2, mul2(P, P));
        float sl, sh; upk2(ss, sl, sh);
        sl = fmaxf(sl, 1e-16f);
        sh = fmaxf(sh, 1e-16f);
        U64 inv = pk2(rsqrt_ap(sl), rsqrt_ap(sh));
        U64 li  = mul2(LAM, inv);
        U64 K   = fma2(li, Q, OML);
        U64 o0  = fma2(li, P, mul2(Xp0, OML));

        float Klo, Khi; upk2(K, Klo, Khi);
        float olo, ohi; upk2(o0, olo, ohi);

        float4 a0 = in4[2 * mA + 0];
        float4 a1 = in4[2 * mA + 1];
        a0.x = olo;
        a0.y *= Klo; a0.z *= Klo; a0.w *= Klo;
        a1.x *= Klo; a1.y *= Klo; a1.z *= Klo; a1.w *= Klo;
        out4[2 * mA + 0] = a0;
        out4[2 * mA + 1] = a1;

        float4 b0 = in4[2 * mB + 0];
        float4 b1v = in4[2 * mB + 1];
        b0.x = ohi;
        b0.y *= Khi; b0.z *= Khi; b0.w *= Khi;
        b1v.x *= Khi; b1v.y *= Khi; b1v.z *= Khi; b1v.w *= Khi;
        out4[2 * mB + 0] = b0;
        out4[2 * mB + 1] = b1v;
    }
    // ---- epilogue stream Y ----
    {
        U64 n2 = mul2(Ynp, Ynp);
        U64 r2 = mul2(Yp0, Yp0);
        U64 s2 = fma2(n2, N1, r2);
        U64 u3 = fma2(n2, N3, r2);
        U64 s3 = mul2(Yp0, u3);
        U64 t3 = fma2(r2, TWO, s2);
        U64 P  = fma2(aAY, Yp0, fma2(aBY, s2, mul2(aCY, s3)));
        U64 tr = add2(Yp0, Yp0);
        U64 Q  = fma2(aCY, t3, fma2(aBY, tr, aAY));
        U64 ss = fma2(mul2(Q, Q), n2, mul2(P, P));
        float sl, sh; upk2(ss, sl, sh);
        sl = fmaxf(sl, 1e-16f);
        sh = fmaxf(sh, 1e-16f);
        U64 inv = pk2(rsqrt_ap(sl), rsqrt_ap(sh));
        U64 li  = mul2(LAM, inv);
        U64 K   = fma2(li, Q, OML);
        U64 o0  = fma2(li, P, mul2(Yp0, OML));

        float Klo, Khi; upk2(K, Klo, Khi);
        float olo, ohi; upk2(o0, olo, ohi);

        float4 a0 = in4[2 * mC + 0];
        float4 a1 = in4[2 * mC + 1];
        a0.x = olo;
        a0.y *= Klo; a0.z *= Klo; a0.w *= Klo;
        a1.x *= Klo; a1.y *= Klo; a1.z *= Klo; a1.w *= Klo;
        out4[2 * mC + 0] = a0;
        out4[2 * mC + 1] = a1;

        float4 b0 = in4[2 * mD + 0];
        float4 b1v = in4[2 * mD + 1];
        b0.x = ohi;
        b0.y *= Khi; b0.z *= Khi; b0.w *= Khi;
        b1v.x *= Khi; b1v.y *= Khi; b1v.z *= Khi; b1v.w *= Khi;
        out4[2 * mD + 0] = b0;
        out4[2 * mD + 1] = b1v;
    }
}

extern "C" void kernel_launch(void* const* d_in, const int* in_sizes, int n_in,
                              void* d_out, int out_size)
{
    const float* o     = (const float*)d_in[0];
    const float* W1    = (const float*)d_in[1];
    const float* b1    = (const float*)d_in[2];
    const float* W2    = (const float*)d_in[3];
    const float* b2    = (const float*)d_in[4];
    const float* alpha = (const float*)d_in[5];

    const int total = in_sizes[0];          // 33,554,432 floats
    const int octs  = total / 8;            // 4,194,304 octonions
    const int blocks = octs / OPB;          // 8192

    g2ff_kernel<<<blocks, TPB>>>((const float4*)o, W1, b1, W2, b2, alpha,
                                 (float4*)d_out);
}